// round 13
// baseline (speedup 1.0000x reference)
#include <cuda_runtime.h>
#include <cuda_fp16.h>
#include <math.h>

#define BB 1024
#define SS 128
#define DD 256
#define EE 128
#define NHH 8
#define INV_SQRT_HD 0.17677669529663687f
#define RSB 528
#define EGP 272

#define PDL_WAIT()   asm volatile("griddepcontrol.wait;" ::: "memory")
#define PDL_LAUNCH() asm volatile("griddepcontrol.launch_dependents;")

// ---------------- device scratch ----------------
__device__ __align__(16) __half g_Wt [1024 * 256];
__device__ __align__(16) __half g_Wkn[256 * 256];
__device__ __align__(16) __half g_Wet[768 * 128];
__device__ __align__(16) __half g_EFh[1024 * 128];
__device__ __align__(16) __half g_Qh [2048 * 256];
__device__ __align__(16) __half g_R  [(size_t)BB * 16 * 256];
__device__ __align__(16) __half g_Y  [(size_t)BB * 16 * 256];
__device__ __align__(16) __half g_AO [2048 * 256];
__device__ __align__(16) float  g_pre[(size_t)BB * 768];
__device__ __align__(16) float  g_bkd[BB * 16];
__device__ __align__(16) float  g_a  [BB * DD];
__device__ __align__(16) float  g_s2 [BB * DD];
__device__ __align__(16) float  g_eb [BB * NHH];
__device__ __align__(16) float  g_hs [BB * NHH];

// ---------------- helpers ----------------
__device__ __forceinline__ unsigned smem_u32(const void* p) {
    unsigned a;
    asm("{ .reg .u64 t; cvta.to.shared.u64 t, %1; cvt.u32.u64 %0, t; }" : "=r"(a) : "l"(p));
    return a;
}
__device__ __forceinline__ void ldsm4(unsigned* r, unsigned a) {
    asm volatile("ldmatrix.sync.aligned.m8n8.x4.shared.b16 {%0,%1,%2,%3}, [%4];"
                 : "=r"(r[0]), "=r"(r[1]), "=r"(r[2]), "=r"(r[3]) : "r"(a));
}
__device__ __forceinline__ void ldsm4t(unsigned* r, unsigned a) {
    asm volatile("ldmatrix.sync.aligned.m8n8.x4.trans.shared.b16 {%0,%1,%2,%3}, [%4];"
                 : "=r"(r[0]), "=r"(r[1]), "=r"(r[2]), "=r"(r[3]) : "r"(a));
}
__device__ __forceinline__ void mma16816(float c[4], const unsigned a[4],
                                         unsigned b0, unsigned b1) {
    asm volatile("mma.sync.aligned.m16n8k16.row.col.f32.f16.f16.f32 "
        "{%0,%1,%2,%3}, {%4,%5,%6,%7}, {%8,%9}, {%0,%1,%2,%3};"
        : "+f"(c[0]), "+f"(c[1]), "+f"(c[2]), "+f"(c[3])
        : "r"(a[0]), "r"(a[1]), "r"(a[2]), "r"(a[3]), "r"(b0), "r"(b1));
}

// =====================================================================
// prep (608 CTAs)
// =====================================================================
__global__ void __launch_bounds__(256)
prep_kernel(const float* __restrict__ Wk, const float* __restrict__ Wv,
            const float* __restrict__ Wq, const float* __restrict__ Wo,
            const float* __restrict__ Wg, const float* __restrict__ Ws,
            const float* __restrict__ Wh, const float* __restrict__ EF)
{
    __shared__ float tile[32][33];
    const int bid = blockIdx.x, t = threadIdx.x;
    const int tx = t & 31, ty = t >> 5;

    if (bid < 256) {
        const int n0 = (bid & 31) * 32, k0 = (bid >> 5) * 32;
        const float* W = (n0 < 256) ? Wk : (n0 < 512) ? Wv : (n0 < 768) ? Wq : Wo;
        const int ncol = n0 & 255;
        #pragma unroll
        for (int i = 0; i < 4; i++) {
            int k = k0 + ty + i * 8;
            tile[ty + i * 8][tx] = W[k * 256 + ncol + tx];
        }
        __syncthreads();
        #pragma unroll
        for (int i = 0; i < 4; i++) {
            int n = n0 + ty + i * 8;
            g_Wt[(size_t)n * 256 + k0 + tx] = __float2half(tile[tx][ty + i * 8]);
        }
    } else if (bid < 352) {
        const int idx = bid - 256;
        const int n0 = (idx % 24) * 32, k0 = (idx / 24) * 32;
        const float* W = (n0 < 256) ? Wg : (n0 < 512) ? Ws : Wh;
        const int ncol = n0 & 255;
        #pragma unroll
        for (int i = 0; i < 4; i++) {
            int k = k0 + ty + i * 8;
            tile[ty + i * 8][tx] = W[k * 256 + ncol + tx];
        }
        __syncthreads();
        #pragma unroll
        for (int i = 0; i < 4; i++) {
            int n = n0 + ty + i * 8;
            g_Wet[(size_t)n * 128 + k0 + tx] = __float2half(tile[tx][ty + i * 8]);
        }
    } else {
        const int i = (bid - 352) * 256 + t;
        if (i < 32768) {
            float2 v = reinterpret_cast<const float2*>(Wk)[i];
            reinterpret_cast<__half2*>(g_Wkn)[i] = __floats2half2_rn(v.x, v.y);
        }
        float2 v = reinterpret_cast<const float2*>(EF)[i];
        reinterpret_cast<__half2*>(g_EFh)[i] = __floats2half2_rn(v.x, v.y);
    }
    PDL_LAUNCH();
}

// =====================================================================
// gemm32 body.  mode0: A=X gather -> wait -> B.  mode1: B -> wait -> A=g_AO.
// =====================================================================
#define G32_B    16896u
#define G32_SMEM (16896 + 128 * RSB)

__device__ __forceinline__ void gemm32_body(
    int mode, const float* __restrict__ bias, float* __restrict__ outp,
    const float* __restrict__ X, int m0, int ny, char* sm, unsigned smb)
{
    const int t = threadIdx.x, w = t >> 5, lane = t & 31;
    const __half* Bg = g_Wt + (size_t)((mode ? 768 : 512) + ny * 128) * 256;

    if (mode == 0) {
        #pragma unroll
        for (int i = 0; i < 8; i++) {
            int idx = t + i * 256;
            int r = idx >> 6, c4 = idx & 63;
            const int row = m0 + r, b = row >> 1, s = (row & 1) ? 127 : 63;
            float4 v = reinterpret_cast<const float4*>(X)[((size_t)b * SS + s) * 64 + c4];
            __half2 h0 = __floats2half2_rn(v.x, v.y);
            __half2 h1 = __floats2half2_rn(v.z, v.w);
            uint2 pk;
            pk.x = *reinterpret_cast<unsigned*>(&h0);
            pk.y = *reinterpret_cast<unsigned*>(&h1);
            *reinterpret_cast<uint2*>(sm + (size_t)r * RSB + c4 * 8) = pk;
        }
        PDL_WAIT();
        #pragma unroll
        for (int i = 0; i < 16; i++) {
            int idx = t + i * 256;
            int r = idx >> 5, c = idx & 31;
            *reinterpret_cast<uint4*>(sm + G32_B + (size_t)r * RSB + c * 16) =
                reinterpret_cast<const uint4*>(Bg + (size_t)r * 256)[c];
        }
    } else {
        #pragma unroll
        for (int i = 0; i < 16; i++) {
            int idx = t + i * 256;
            int r = idx >> 5, c = idx & 31;
            *reinterpret_cast<uint4*>(sm + G32_B + (size_t)r * RSB + c * 16) =
                reinterpret_cast<const uint4*>(Bg + (size_t)r * 256)[c];
        }
        PDL_WAIT();
        #pragma unroll
        for (int i = 0; i < 4; i++) {
            int idx = t + i * 256;
            int r = idx >> 5, c = idx & 31;
            *reinterpret_cast<uint4*>(sm + (size_t)r * RSB + c * 16) =
                reinterpret_cast<const uint4*>(g_AO + (size_t)(m0 + r) * 256)[c];
        }
    }
    __syncthreads();

    const int wm = (w & 1) * 16, wn = (w >> 1) * 32;
    float acc[4][4];
    #pragma unroll
    for (int n = 0; n < 4; n++)
        #pragma unroll
        for (int e = 0; e < 4; e++) acc[n][e] = 0.0f;
    const unsigned aA = smb + (unsigned)(wm + (lane & 15)) * RSB + (lane >> 4) * 16;
    const unsigned bA = smb + G32_B + (unsigned)(wn + (lane & 7) + ((lane >> 4) << 3)) * RSB
                        + ((lane >> 3) & 1) * 16;
    #pragma unroll
    for (int ks = 0; ks < 16; ks++) {
        const unsigned ko = ks * 32u;
        unsigned a[4], bb[4];
        ldsm4(a, aA + ko);
        #pragma unroll
        for (int g = 0; g < 2; g++) {
            ldsm4(bb, bA + g * (16u * RSB) + ko);
            mma16816(acc[2 * g],     a, bb[0], bb[1]);
            mma16816(acc[2 * g + 1], a, bb[2], bb[3]);
        }
    }
    #pragma unroll
    for (int nt = 0; nt < 4; nt++) {
        const int col = ny * 128 + wn + nt * 8 + (lane & 3) * 2;
        const int r0 = m0 + wm + (lane >> 2);
        const float b0 = bias[col], b1 = bias[col + 1];
        if (mode == 0) {
            *reinterpret_cast<__half2*>(&g_Qh[(size_t)r0 * 256 + col]) =
                __floats2half2_rn(acc[nt][0] + b0, acc[nt][1] + b1);
            *reinterpret_cast<__half2*>(&g_Qh[(size_t)(r0 + 8) * 256 + col]) =
                __floats2half2_rn(acc[nt][2] + b0, acc[nt][3] + b1);
        } else {
            *reinterpret_cast<float2*>(&outp[(size_t)r0 * 256 + col]) =
                make_float2(acc[nt][0] + b0, acc[nt][1] + b1);
            *reinterpret_cast<float2*>(&outp[(size_t)(r0 + 8) * 256 + col]) =
                make_float2(acc[nt][2] + b0, acc[nt][3] + b1);
        }
    }
    PDL_LAUNCH();
}

// =====================================================================
// mid1: edge GEMM (0..95) + Q projection (96..223)
// =====================================================================
#define EG_B (64 * EGP)

__global__ void __launch_bounds__(256)
mid1_kernel(const float* __restrict__ bg, const float* __restrict__ bs,
            const float* __restrict__ bh, const float* __restrict__ bq,
            const float* __restrict__ X)
{
    extern __shared__ __align__(16) char sm[];
    const unsigned smb = smem_u32(sm);
    const int bid = blockIdx.x, t = threadIdx.x, w = t >> 5, lane = t & 31;

    if (bid >= 96) {
        const int idx = bid - 96;
        gemm32_body(0, bq, nullptr, X, (idx & 63) * 32, idx >> 6, sm, smb);
        return;
    }
    PDL_WAIT();
    const int m0 = (bid % 16) * 64, ny = bid / 16;
    #pragma unroll
    for (int i = 0; i < 4; i++) {
        int idx = t + i * 256;
        int r = idx >> 4, c = idx & 15;
        *reinterpret_cast<uint4*>(sm + (size_t)r * EGP + c * 16) =
            reinterpret_cast<const uint4*>(g_EFh + (size_t)(m0 + r) * 128)[c];
    }
    #pragma unroll
    for (int i = 0; i < 8; i++) {
        int idx = t + i * 256;
        int r = idx >> 4, c = idx & 15;
        *reinterpret_cast<uint4*>(sm + EG_B + (size_t)r * EGP + c * 16) =
            reinterpret_cast<const uint4*>(g_Wet + (size_t)(ny * 128 + r) * 128)[c];
    }
    __syncthreads();

    const int wm = (w & 1) * 32, wn = (w >> 1) * 32;
    float acc[2][4][4];
    #pragma unroll
    for (int mt = 0; mt < 2; mt++)
        #pragma unroll
        for (int n = 0; n < 4; n++)
            #pragma unroll
            for (int e = 0; e < 4; e++) acc[mt][n][e] = 0.0f;
    const unsigned aA = smb + (unsigned)(wm + (lane & 15)) * EGP + (lane >> 4) * 16;
    const unsigned bA = smb + EG_B + (unsigned)(wn + (lane & 7) + ((lane >> 4) << 3)) * EGP
                        + ((lane >> 3) & 1) * 16;
    #pragma unroll
    for (int ks = 0; ks < 8; ks++) {
        const unsigned ko = ks * 32u;
        unsigned a0[4], a1[4], bb[4];
        ldsm4(a0, aA + ko);
        ldsm4(a1, aA + 16u * EGP + ko);
        #pragma unroll
        for (int g = 0; g < 2; g++) {
            ldsm4(bb, bA + g * (16u * EGP) + ko);
            mma16816(acc[0][2 * g],     a0, bb[0], bb[1]);
            mma16816(acc[0][2 * g + 1], a0, bb[2], bb[3]);
            mma16816(acc[1][2 * g],     a1, bb[0], bb[1]);
            mma16816(acc[1][2 * g + 1], a1, bb[2], bb[3]);
        }
    }
    const float* bp = (ny < 2) ? bg : (ny < 4) ? bs : bh;
    const int boff = (ny & 1) * 128;
    #pragma unroll
    for (int mt = 0; mt < 2; mt++)
        #pragma unroll
        for (int nt = 0; nt < 4; nt++) {
            const int col = wn + nt * 8 + (lane & 3) * 2;
            const int C = ny * 128 + col;
            const int r0 = m0 + wm + mt * 16 + (lane >> 2);
            const float b0 = bp[boff + col], b1 = bp[boff + col + 1];
            *reinterpret_cast<float2*>(&g_pre[(size_t)r0 * 768 + C]) =
                make_float2(acc[mt][nt][0] + b0, acc[mt][nt][1] + b1);
            *reinterpret_cast<float2*>(&g_pre[(size_t)(r0 + 8) * 768 + C]) =
                make_float2(acc[mt][nt][2] + b0, acc[mt][nt][3] + b1);
        }
    PDL_LAUNCH();
}

// =====================================================================
// mid2: r kernel (0..255) + edge combine (256..1279)
// =====================================================================
__global__ void __launch_bounds__(256)
mid2_kernel(const float* __restrict__ EF,
            const float* __restrict__ Wbias, const float* __restrict__ bbias,
            const float* __restrict__ Whead, const float* __restrict__ bhead,
            const float* __restrict__ bk)
{
    __shared__ __align__(16) __half As[64 * 40];
    __shared__ __align__(16) __half Bs[256 * 40];
    __shared__ float ef[EE];
    const int bid = blockIdx.x, t = threadIdx.x, w = t >> 5, lane = t & 31;

    if (bid >= 256) {
        const int b = bid - 256;
        if (t < EE) ef[t] = EF[(size_t)b * EE + t];
        PDL_WAIT();
        __syncthreads();
        const float G = g_pre[(size_t)b * 768 + t];
        const float S = g_pre[(size_t)b * 768 + 256 + t];
        const float H = g_pre[(size_t)b * 768 + 512 + t];
        const float gate = 1.0f / (1.0f + __expf(-G));
        g_a [b * DD + t] = gate * (1.0f + tanhf(S));
        g_s2[b * DD + t] = gate * H;

        float ab = 0.0f, ah = 0.0f;
        #pragma unroll
        for (int j = 0; j < 4; j++) {
            const int e = lane + 32 * j;
            const float f = ef[e];
            ab += f * Wbias[e * NHH + w];
            ah += f * Whead[e * NHH + w];
        }
        #pragma unroll
        for (int o = 16; o > 0; o >>= 1) {
            ab += __shfl_xor_sync(0xffffffffu, ab, o);
            ah += __shfl_xor_sync(0xffffffffu, ah, o);
        }
        if (lane == 0) {
            g_eb[b * NHH + w] = bbias[w] + ab;
            g_hs[b * NHH + w] = (1.0f + tanhf(bhead[w] + ah)) * INV_SQRT_HD;
        }
        PDL_LAUNCH();
        return;
    }
    const int m0 = (bid & 31) * 64, h = bid >> 5;
    #pragma unroll
    for (int i = 0; i < 4; i++) {
        int idx = t + i * 256;
        int r = idx >> 2, c4 = idx & 3;
        reinterpret_cast<uint4*>(Bs + r * 40)[c4] =
            reinterpret_cast<const uint4*>(g_Wkn + (size_t)r * 256 + h * 32)[c4];
    }
    PDL_WAIT();
    {
        int r = t >> 2, c4 = t & 3;
        reinterpret_cast<uint4*>(As + r * 40)[c4] =
            reinterpret_cast<const uint4*>(g_Qh + (size_t)(m0 + r) * 256 + h * 32)[c4];
    }
    __syncthreads();

    if (t < 64) {
        float s = 0.0f;
        #pragma unroll
        for (int d = 0; d < 32; d++)
            s += __half2float(As[t * 40 + d]) * bk[h * 32 + d];
        g_bkd[(size_t)((m0 + t) >> 1) * 16 + h * 2 + ((m0 + t) & 1)] = s;
    }

    const int wm = (w & 3) * 16, wn = (w >> 2) * 128;
    float acc[16][4];
    #pragma unroll
    for (int n = 0; n < 16; n++)
        #pragma unroll
        for (int e = 0; e < 4; e++) acc[n][e] = 0.0f;
    const unsigned aA = smem_u32(As) + (unsigned)(wm + (lane & 15)) * 80 + (lane >> 4) * 16;
    const unsigned bA = smem_u32(Bs) + (unsigned)(wn + (lane & 7) + ((lane >> 4) << 3)) * 80
                        + ((lane >> 3) & 1) * 16;
    #pragma unroll
    for (int ks = 0; ks < 2; ks++) {
        const unsigned ko = ks * 32u;
        unsigned a[4];
        ldsm4(a, aA + ko);
        #pragma unroll
        for (int g = 0; g < 8; g++) {
            unsigned bb[4];
            ldsm4(bb, bA + g * (16u * 80) + ko);
            mma16816(acc[2 * g],     a, bb[0], bb[1]);
            mma16816(acc[2 * g + 1], a, bb[2], bb[3]);
        }
    }
    #pragma unroll
    for (int nt = 0; nt < 16; nt++) {
        const int c = wn + nt * 8 + (lane & 3) * 2;
        #pragma unroll
        for (int half_ = 0; half_ < 2; half_++) {
            const int rr = m0 + wm + (lane >> 2) + half_ * 8;
            const int bidx = rr >> 1, p = h * 2 + (rr & 1);
            *reinterpret_cast<__half2*>(&g_R[((size_t)bidx * 16 + p) * 256 + c]) =
                __floats2half2_rn(acc[nt][2 * half_], acc[nt][2 * half_ + 1]);
        }
    }
    PDL_LAUNCH();
}

// =====================================================================
// FUSED v4: persistent, double-buffered.  Grid 148, 1 CTA/SM.
//   Next batch's X tile is loaded (LDG batches of 8 interleaved with the
//   scores MMA) into the alternate smem buffer while computing batch b.
// =====================================================================
#define FX_XH0  0
#define FX_XH1  67584
#define FX_RR   135168
#define FX_P    143616
#define FX_S    152320
#define FX_SMEM 160768

__global__ void __launch_bounds__(256)
fused_kernel(const float* __restrict__ X)
{
    extern __shared__ __align__(16) char sm[];
    const unsigned smb = smem_u32(sm);
    float* S = reinterpret_cast<float*>(sm + FX_S);
    const int t = threadIdx.x, w = t >> 5, lane = t & 31;

    // prologue: load X(blockIdx.x) into XH0 — before PDL wait (overlaps upstream)
    {
        const float4* X4 = reinterpret_cast<const float4*>(X) + (size_t)blockIdx.x * SS * 64;
        #pragma unroll 8
        for (int i = 0; i < 32; i++) {
            int idx = t + i * 256;
            int r = idx >> 6, kq = idx & 63;
            float4 v = X4[idx];
            __half2 h0 = __floats2half2_rn(v.x, v.y);
            __half2 h1 = __floats2half2_rn(v.z, v.w);
            uint2 pk;
            pk.x = *reinterpret_cast<unsigned*>(&h0);
            pk.y = *reinterpret_cast<unsigned*>(&h1);
            *reinterpret_cast<uint2*>(sm + FX_XH0 + (size_t)r * RSB + kq * 8) = pk;
        }
    }
    PDL_WAIT();

    unsigned curXH = FX_XH0, nxtXH = FX_XH1;
    for (int b = blockIdx.x; b < BB; b += 148) {
        const int bn = b + 148;
        const bool hn = (bn < BB);
        // R(b) -> smem
        #pragma unroll
        for (int i = 0; i < 2; i++) {
            int idx = t + i * 256;
            int r = idx >> 5, c = idx & 31;
            *reinterpret_cast<uint4*>(sm + FX_RR + (size_t)r * RSB + c * 16) =
                reinterpret_cast<const uint4*>(g_R + ((size_t)b * 16 + r) * 256)[c];
        }
        __syncthreads();   // R + XH[cur] ready; prior-iter reads all done

        // ---- scores (warp w -> keys [16w,16w+16)) + interleaved next-tile load ----
        const float4* Xn = reinterpret_cast<const float4*>(X) + (size_t)bn * SS * 64;
        float sa[2][4];
        #pragma unroll
        for (int n = 0; n < 2; n++)
            #pragma unroll
            for (int e = 0; e < 4; e++) sa[n][e] = 0.0f;
        const unsigned aA = smb + FX_RR + (unsigned)(lane & 15) * RSB + (lane >> 4) * 16;
        const unsigned bA = smb + curXH + (unsigned)(w * 16 + (lane & 7) + ((lane >> 4) << 3)) * RSB
                            + ((lane >> 3) & 1) * 16;
        #pragma unroll
        for (int kb = 0; kb < 4; kb++) {
            float4 rx[8];
            if (hn) {
                #pragma unroll
                for (int j = 0; j < 8; j++) rx[j] = Xn[t + (kb * 8 + j) * 256];
            }
            #pragma unroll
            for (int q = 0; q < 4; q++) {
                const unsigned ko = (unsigned)(kb * 4 + q) * 32u;
                unsigned a[4], bb[4];
                ldsm4(a, aA + ko);
                ldsm4(bb, bA + ko);
                mma16816(sa[0], a, bb[0], bb[1]);
                mma16816(sa[1], a, bb[2], bb[3]);
            }
            if (hn) {
                #pragma unroll
                for (int j = 0; j < 8; j++) {
                    int idx = t + (kb * 8 + j) * 256;
                    int r = idx >> 6, kq = idx & 63;
                    __half2 h0 = __floats2half2_rn(rx[j].x, rx[j].y);
                    __half2 h1 = __floats2half2_rn(rx[j].z, rx[j].w);
                    uint2 pk;
                    pk.x = *reinterpret_cast<unsigned*>(&h0);
                    pk.y = *reinterpret_cast<unsigned*>(&h1);
                    *reinterpret_cast<uint2*>(sm + nxtXH + (size_t)r * RSB + kq * 8) = pk;
                }
            }
        }
        #pragma unroll
        for (int nt = 0; nt < 2; nt++) {
            const int c0 = w * 16 + nt * 8 + (lane & 3) * 2;
            const int p0 = lane >> 2;
            S[p0 * 128 + c0]           = sa[nt][0];
            S[p0 * 128 + c0 + 1]       = sa[nt][1];
            S[(p0 + 8) * 128 + c0]     = sa[nt][2];
            S[(p0 + 8) * 128 + c0 + 1] = sa[nt][3];
        }
        __syncthreads();   // S complete; XH[nxt] complete

        // ---- softmax: warp w = head w ----
        const float ebv = g_eb[b * NHH + w];
        const float hsv = g_hs[b * NHH + w];
        #pragma unroll
        for (int qi = 0; qi < 2; qi++) {
            const int p = w * 2 + qi;
            const int kb2 = qi ? 63 : 127;
            const float bkd = g_bkd[(size_t)b * 16 + p];
            float sv[4];
            #pragma unroll
            for (int j = 0; j < 4; j++) {
                const int k = lane + 32 * j;
                float s = (S[p * 128 + k] + bkd) * hsv;
                if (k == kb2) s += ebv;
                sv[j] = s;
            }
            float m = fmaxf(fmaxf(sv[0], sv[1]), fmaxf(sv[2], sv[3]));
            #pragma unroll
            for (int o = 16; o > 0; o >>= 1) m = fmaxf(m, __shfl_xor_sync(0xffffffffu, m, o));
            float e[4], sum = 0.0f;
            #pragma unroll
            for (int j = 0; j < 4; j++) { e[j] = __expf(sv[j] - m); sum += e[j]; }
            #pragma unroll
            for (int o = 16; o > 0; o >>= 1) sum += __shfl_xor_sync(0xffffffffu, sum, o);
            const float inv = 1.0f / sum;
            #pragma unroll
            for (int j = 0; j < 4; j++) {
                const int k = lane + 32 * j;
                const float pv = e[j] * inv;
                const __half hi = __float2half_rn(pv);
                const __half lo = __float2half_rn(pv - __half2float(hi));
                *reinterpret_cast<__half*>(sm + FX_P + (size_t)p * 272 + k * 2) = hi;
                *reinterpret_cast<__half*>(sm + FX_P + (size_t)(p + 16) * 272 + k * 2) = lo;
            }
        }
        __syncthreads();

        // ---- y: [Phi;Plo](32x128) @ X(128x256); warp w -> cols w*32 ----
        {
            float ya[2][4][4];
            #pragma unroll
            for (int mt = 0; mt < 2; mt++)
                #pragma unroll
                for (int n = 0; n < 4; n++)
                    #pragma unroll
                    for (int e = 0; e < 4; e++) ya[mt][n][e] = 0.0f;
            const unsigned pA = smb + FX_P + (unsigned)(lane & 15) * 272 + (lane >> 4) * 16;
            const unsigned bT = smb + curXH
                + (unsigned)((lane & 7) + ((lane >> 3) & 1) * 8) * RSB
                + (lane >> 4) * 16 + (unsigned)(w * 32) * 2;
            #pragma unroll
            for (int ks = 0; ks < 8; ks++) {
                unsigned a0[4], a1[4], b0[4], b1[4];
                ldsm4(a0, pA + ks * 32u);
                ldsm4(a1, pA + 16u * 272 + ks * 32u);
                ldsm4t(b0, bT + ks * (16u * RSB));
                ldsm4t(b1, bT + 32u + ks * (16u * RSB));
                mma16816(ya[0][0], a0, b0[0], b0[1]);
                mma16816(ya[0][1], a0, b0[2], b0[3]);
                mma16816(ya[0][2], a0, b1[0], b1[1]);
                mma16816(ya[0][3], a0, b1[2], b1[3]);
                mma16816(ya[1][0], a1, b0[0], b0[1]);
                mma16816(ya[1][1], a1, b0[2], b0[3]);
                mma16816(ya[1][2], a1, b1[0], b1[1]);
                mma16816(ya[1][3], a1, b1[2], b1[3]);
            }
            #pragma unroll
            for (int nt = 0; nt < 4; nt++) {
                const int c0 = w * 32 + nt * 8 + (lane & 3) * 2;
                const int p0 = lane >> 2;
                *reinterpret_cast<__half2*>(&g_Y[((size_t)b * 16 + p0) * 256 + c0]) =
                    __floats2half2_rn(ya[0][nt][0] + ya[1][nt][0], ya[0][nt][1] + ya[1][nt][1]);
                *reinterpret_cast<__half2*>(&g_Y[((size_t)b * 16 + p0 + 8) * 256 + c0]) =
                    __floats2half2_rn(ya[0][nt][2] + ya[1][nt][2], ya[0][nt][3] + ya[1][nt][3]);
            }
        }
        const unsigned tmp = curXH; curXH = nxtXH; nxtXH = tmp;
        // loop-top __syncthreads orders next-iter R overwrite & buffer reuse
    }
    PDL_LAUNCH();
}

// =====================================================================
// AOh: per-head GEMM with gating epilogue.  B first, wait, then A.
// =====================================================================
#define AO_B    33792u
#define AO_SMEM (33792 + 32 * RSB)

__global__ void __launch_bounds__(256)
aoh_kernel(const float* __restrict__ bv)
{
    extern __shared__ __align__(16) char sm[];
    const unsigned smb = smem_u32(sm);
    const int t = threadIdx.x, w = t >> 5, lane = t & 31;
    const int b0 = (blockIdx.x & 31) * 32, h = blockIdx.x >> 5;

    #pragma unroll
    for (int i = 0; i < 4; i++) {
        int idx = t + i * 256;
        int r = idx >> 5, c = idx & 31;
        *reinterpret_cast<uint4*>(sm + AO_B + (size_t)r * RSB + c * 16) =
            reinterpret_cast<const uint4*>(g_Wt + (size_t)(256 + h * 32 + r) * 256)[c];
    }
    PDL_WAIT();
    #pragma unroll
    for (int i = 0; i < 8; i++) {
        int idx = t + i * 256;
        int rr = idx >> 5, c = idx & 31;
        const size_t src = ((size_t)(b0 + (rr >> 1)) * 16 + h * 2 + (rr & 1)) * 256;
        *reinterpret_cast<uint4*>(sm + (size_t)rr * RSB + c * 16) =
            reinterpret_cast<const uint4*>(g_Y + src)[c];
    }
    __syncthreads();

    const int wm = (w & 3) * 16, wn = (w >> 2) * 16;
    float acc[2][4];
    #pragma unroll
    for (int n = 0; n < 2; n++)
        #pragma unroll
        for (int e = 0; e < 4; e++) acc[n][e] = 0.0f;
    const unsigned aA = smb + (unsigned)(wm + (lane & 15)) * RSB + (lane >> 4) * 16;
    const unsigned bA = smb + AO_B + (unsigned)(wn + (lane & 7) + ((lane >> 4) << 3)) * RSB
                        + ((lane >> 3) & 1) * 16;
    #pragma unroll
    for (int ks = 0; ks < 16; ks++) {
        const unsigned ko = ks * 32u;
        unsigned a[4], bb[4];
        ldsm4(a, aA + ko);
        ldsm4(bb, bA + ko);
        mma16816(acc[0], a, bb[0], bb[1]);
        mma16816(acc[1], a, bb[2], bb[3]);
    }
    #pragma unroll
    for (int nt = 0; nt < 2; nt++) {
        const int col = wn + nt * 8 + (lane & 3) * 2;
        const int C = h * 32 + col;
        const float b0f = bv[C], b1f = bv[C + 1];
        #pragma unroll
        for (int half_ = 0; half_ < 2; half_++) {
            const int rr = wm + (lane >> 2) + half_ * 8;
            const int bb_ = b0 + (rr >> 1), qi = rr & 1;
            const float a0 = g_a[bb_ * DD + C],  a1 = g_a[bb_ * DD + C + 1];
            const float s0 = g_s2[bb_ * DD + C], s1 = g_s2[bb_ * DD + C + 1];
            *reinterpret_cast<__half2*>(&g_AO[(size_t)(bb_ * 2 + qi) * 256 + C]) =
                __floats2half2_rn((acc[nt][2 * half_]     + b0f) * a0 + s0,
                                  (acc[nt][2 * half_ + 1] + b1f) * a1 + s1);
        }
    }
    PDL_LAUNCH();
}

// =====================================================================
// final: O projection
// =====================================================================
__global__ void __launch_bounds__(256)
final_kernel(const float* __restrict__ bo, float* __restrict__ out,
             const float* __restrict__ X)
{
    extern __shared__ __align__(16) char sm[];
    gemm32_body(1, bo, out, X, (blockIdx.x & 63) * 32, blockIdx.x >> 6,
                sm, smem_u32(sm));
}

// =====================================================================
extern "C" void kernel_launch(void* const* d_in, const int* in_sizes, int n_in,
                              void* d_out, int out_size)
{
    (void)in_sizes; (void)n_in; (void)out_size;
    const float* X      = (const float*)d_in[0];
    const float* EF     = (const float*)d_in[1];
    const float* Wq     = (const float*)d_in[2];
    const float* bq     = (const float*)d_in[3];
    const float* Wk     = (const float*)d_in[4];
    const float* bk     = (const float*)d_in[5];
    const float* Wv     = (const float*)d_in[6];
    const float* bv     = (const float*)d_in[7];
    const float* Wo     = (const float*)d_in[8];
    const float* bo     = (const float*)d_in[9];
    const float* Wbias  = (const float*)d_in[10];
    const float* bbias  = (const float*)d_in[11];
    const float* Wgate  = (const float*)d_in[12];
    const float* bgate  = (const float*)d_in[13];
    const float* Wscale = (const float*)d_in[14];
    const float* bscale = (const float*)d_in[15];
    const float* Wshift = (const float*)d_in[16];
    const float* bshift = (const float*)d_in[17];
    const float* Whead  = (const float*)d_in[18];
    const float* bhead  = (const float*)d_in[19];
    float* out = (float*)d_out;

    cudaFuncSetAttribute(mid1_kernel,  cudaFuncAttributeMaxDynamicSharedMemorySize, G32_SMEM);
    cudaFuncSetAttribute(fused_kernel, cudaFuncAttributeMaxDynamicSharedMemorySize, FX_SMEM);
    cudaFuncSetAttribute(aoh_kernel,   cudaFuncAttributeMaxDynamicSharedMemorySize, AO_SMEM);
    cudaFuncSetAttribute(final_kernel, cudaFuncAttributeMaxDynamicSharedMemorySize, G32_SMEM);

    prep_kernel<<<608, 256>>>(Wk, Wv, Wq, Wo, Wgate, Wscale, Wshift, EF);

    cudaLaunchAttribute at[1];
    at[0].id = cudaLaunchAttributeProgrammaticStreamSerialization;
    at[0].val.programmaticStreamSerializationAllowed = 1;
    cudaLaunchConfig_t cfg = {};
    cfg.blockDim = dim3(256, 1, 1);
    cfg.attrs = at;
    cfg.numAttrs = 1;
    cfg.stream = 0;

    cfg.gridDim = dim3(224, 1, 1); cfg.dynamicSmemBytes = G32_SMEM;
    cudaLaunchKernelEx(&cfg, mid1_kernel, bgate, bscale, bshift, bq, X);

    cfg.gridDim = dim3(1280, 1, 1); cfg.dynamicSmemBytes = 0;
    cudaLaunchKernelEx(&cfg, mid2_kernel, EF, Wbias, bbias, Whead, bhead, bk);

    cfg.gridDim = dim3(148, 1, 1); cfg.dynamicSmemBytes = FX_SMEM;
    cudaLaunchKernelEx(&cfg, fused_kernel, X);

    cfg.gridDim = dim3(256, 1, 1); cfg.dynamicSmemBytes = AO_SMEM;
    cudaLaunchKernelEx(&cfg, aoh_kernel, bv);

    cfg.gridDim = dim3(128, 1, 1); cfg.dynamicSmemBytes = G32_SMEM;
    cudaLaunchKernelEx(&cfg, final_kernel, bo, out, X);
}

// round 15
// speedup vs baseline: 1.1899x; 1.1899x over previous
#include <cuda_runtime.h>
#include <cuda_fp16.h>
#include <math.h>

#define BB 1024
#define SS 128
#define DD 256
#define EE 128
#define NHH 8
#define INV_SQRT_HD 0.17677669529663687f
#define RSB 528
#define EGP 272

#define PDL_WAIT()   asm volatile("griddepcontrol.wait;" ::: "memory")
#define PDL_LAUNCH() asm volatile("griddepcontrol.launch_dependents;")

// ---------------- device scratch ----------------
__device__ __align__(16) __half g_Wt [1024 * 256];
__device__ __align__(16) __half g_Wkn[256 * 256];
__device__ __align__(16) __half g_Wet[768 * 128];
__device__ __align__(16) __half g_EFh[1024 * 128];
__device__ __align__(16) __half g_Qh [2048 * 256];
__device__ __align__(16) __half g_R  [(size_t)BB * 16 * 256];
__device__ __align__(16) __half g_Y  [(size_t)BB * 16 * 256];
__device__ __align__(16) __half g_AO [2048 * 256];
__device__ __align__(16) float  g_pre[(size_t)BB * 768];
__device__ __align__(16) float  g_bkd[BB * 16];
__device__ __align__(16) float  g_a  [BB * DD];
__device__ __align__(16) float  g_s2 [BB * DD];
__device__ __align__(16) float  g_eb [BB * NHH];
__device__ __align__(16) float  g_hs [BB * NHH];

// ---------------- helpers ----------------
__device__ __forceinline__ unsigned smem_u32(const void* p) {
    unsigned a;
    asm("{ .reg .u64 t; cvta.to.shared.u64 t, %1; cvt.u32.u64 %0, t; }" : "=r"(a) : "l"(p));
    return a;
}
__device__ __forceinline__ void ldsm4(unsigned* r, unsigned a) {
    asm volatile("ldmatrix.sync.aligned.m8n8.x4.shared.b16 {%0,%1,%2,%3}, [%4];"
                 : "=r"(r[0]), "=r"(r[1]), "=r"(r[2]), "=r"(r[3]) : "r"(a));
}
__device__ __forceinline__ void ldsm4t(unsigned* r, unsigned a) {
    asm volatile("ldmatrix.sync.aligned.m8n8.x4.trans.shared.b16 {%0,%1,%2,%3}, [%4];"
                 : "=r"(r[0]), "=r"(r[1]), "=r"(r[2]), "=r"(r[3]) : "r"(a));
}
__device__ __forceinline__ void mma16816(float c[4], const unsigned a[4],
                                         unsigned b0, unsigned b1) {
    asm volatile("mma.sync.aligned.m16n8k16.row.col.f32.f16.f16.f32 "
        "{%0,%1,%2,%3}, {%4,%5,%6,%7}, {%8,%9}, {%0,%1,%2,%3};"
        : "+f"(c[0]), "+f"(c[1]), "+f"(c[2]), "+f"(c[3])
        : "r"(a[0]), "r"(a[1]), "r"(a[2]), "r"(a[3]), "r"(b0), "r"(b1));
}

// =====================================================================
// prep (608 CTAs)
// =====================================================================
__global__ void __launch_bounds__(256)
prep_kernel(const float* __restrict__ Wk, const float* __restrict__ Wv,
            const float* __restrict__ Wq, const float* __restrict__ Wo,
            const float* __restrict__ Wg, const float* __restrict__ Ws,
            const float* __restrict__ Wh, const float* __restrict__ EF)
{
    __shared__ float tile[32][33];
    const int bid = blockIdx.x, t = threadIdx.x;
    const int tx = t & 31, ty = t >> 5;

    if (bid < 256) {
        const int n0 = (bid & 31) * 32, k0 = (bid >> 5) * 32;
        const float* W = (n0 < 256) ? Wk : (n0 < 512) ? Wv : (n0 < 768) ? Wq : Wo;
        const int ncol = n0 & 255;
        #pragma unroll
        for (int i = 0; i < 4; i++) {
            int k = k0 + ty + i * 8;
            tile[ty + i * 8][tx] = W[k * 256 + ncol + tx];
        }
        __syncthreads();
        #pragma unroll
        for (int i = 0; i < 4; i++) {
            int n = n0 + ty + i * 8;
            g_Wt[(size_t)n * 256 + k0 + tx] = __float2half(tile[tx][ty + i * 8]);
        }
    } else if (bid < 352) {
        const int idx = bid - 256;
        const int n0 = (idx % 24) * 32, k0 = (idx / 24) * 32;
        const float* W = (n0 < 256) ? Wg : (n0 < 512) ? Ws : Wh;
        const int ncol = n0 & 255;
        #pragma unroll
        for (int i = 0; i < 4; i++) {
            int k = k0 + ty + i * 8;
            tile[ty + i * 8][tx] = W[k * 256 + ncol + tx];
        }
        __syncthreads();
        #pragma unroll
        for (int i = 0; i < 4; i++) {
            int n = n0 + ty + i * 8;
            g_Wet[(size_t)n * 128 + k0 + tx] = __float2half(tile[tx][ty + i * 8]);
        }
    } else {
        const int i = (bid - 352) * 256 + t;
        if (i < 32768) {
            float2 v = reinterpret_cast<const float2*>(Wk)[i];
            reinterpret_cast<__half2*>(g_Wkn)[i] = __floats2half2_rn(v.x, v.y);
        }
        float2 v = reinterpret_cast<const float2*>(EF)[i];
        reinterpret_cast<__half2*>(g_EFh)[i] = __floats2half2_rn(v.x, v.y);
    }
    PDL_LAUNCH();
}

// =====================================================================
// gemm64 body: 32-row x 64-col output tile, K=256.
// =====================================================================
#define G64_B    16896u
#define G64_SMEM (16896 + 64 * RSB)
#define MID1_SMEM (192 * EGP)          // 52224: covers edge path AND gemm64 path

__device__ __forceinline__ void gemm64_body(
    int mode, const float* __restrict__ bias, float* __restrict__ outp,
    const float* __restrict__ X, int m0, int ny, char* sm, unsigned smb)
{
    const int t = threadIdx.x, w = t >> 5, lane = t & 31;
    const __half* Bg = g_Wt + (size_t)((mode ? 768 : 512) + ny * 64) * 256;

    if (mode == 0) {
        #pragma unroll
        for (int i = 0; i < 8; i++) {
            int idx = t + i * 256;
            int r = idx >> 6, c4 = idx & 63;
            const int row = m0 + r, b = row >> 1, s = (row & 1) ? 127 : 63;
            float4 v = reinterpret_cast<const float4*>(X)[((size_t)b * SS + s) * 64 + c4];
            __half2 h0 = __floats2half2_rn(v.x, v.y);
            __half2 h1 = __floats2half2_rn(v.z, v.w);
            uint2 pk;
            pk.x = *reinterpret_cast<unsigned*>(&h0);
            pk.y = *reinterpret_cast<unsigned*>(&h1);
            *reinterpret_cast<uint2*>(sm + (size_t)r * RSB + c4 * 8) = pk;
        }
        PDL_WAIT();
        #pragma unroll
        for (int i = 0; i < 8; i++) {
            int idx = t + i * 256;
            int r = idx >> 5, c = idx & 31;
            *reinterpret_cast<uint4*>(sm + G64_B + (size_t)r * RSB + c * 16) =
                reinterpret_cast<const uint4*>(Bg + (size_t)r * 256)[c];
        }
    } else {
        #pragma unroll
        for (int i = 0; i < 8; i++) {
            int idx = t + i * 256;
            int r = idx >> 5, c = idx & 31;
            *reinterpret_cast<uint4*>(sm + G64_B + (size_t)r * RSB + c * 16) =
                reinterpret_cast<const uint4*>(Bg + (size_t)r * 256)[c];
        }
        PDL_WAIT();
        #pragma unroll
        for (int i = 0; i < 4; i++) {
            int idx = t + i * 256;
            int r = idx >> 5, c = idx & 31;
            *reinterpret_cast<uint4*>(sm + (size_t)r * RSB + c * 16) =
                reinterpret_cast<const uint4*>(g_AO + (size_t)(m0 + r) * 256)[c];
        }
    }
    __syncthreads();

    const int wm = (w & 1) * 16, wn = (w >> 1) * 16;
    float acc[2][4];
    #pragma unroll
    for (int n = 0; n < 2; n++)
        #pragma unroll
        for (int e = 0; e < 4; e++) acc[n][e] = 0.0f;
    const unsigned aA = smb + (unsigned)(wm + (lane & 15)) * RSB + (lane >> 4) * 16;
    const unsigned bA = smb + G64_B + (unsigned)(wn + (lane & 7) + ((lane >> 4) << 3)) * RSB
                        + ((lane >> 3) & 1) * 16;
    #pragma unroll
    for (int ks = 0; ks < 16; ks++) {
        const unsigned ko = ks * 32u;
        unsigned a[4], bb[4];
        ldsm4(a, aA + ko);
        ldsm4(bb, bA + ko);
        mma16816(acc[0], a, bb[0], bb[1]);
        mma16816(acc[1], a, bb[2], bb[3]);
    }
    #pragma unroll
    for (int nt = 0; nt < 2; nt++) {
        const int col = ny * 64 + wn + nt * 8 + (lane & 3) * 2;
        const int r0 = m0 + wm + (lane >> 2);
        const float b0 = bias[col], b1 = bias[col + 1];
        if (mode == 0) {
            *reinterpret_cast<__half2*>(&g_Qh[(size_t)r0 * 256 + col]) =
                __floats2half2_rn(acc[nt][0] + b0, acc[nt][1] + b1);
            *reinterpret_cast<__half2*>(&g_Qh[(size_t)(r0 + 8) * 256 + col]) =
                __floats2half2_rn(acc[nt][2] + b0, acc[nt][3] + b1);
        } else {
            *reinterpret_cast<float2*>(&outp[(size_t)r0 * 256 + col]) =
                make_float2(acc[nt][0] + b0, acc[nt][1] + b1);
            *reinterpret_cast<float2*>(&outp[(size_t)(r0 + 8) * 256 + col]) =
                make_float2(acc[nt][2] + b0, acc[nt][3] + b1);
        }
    }
    PDL_LAUNCH();
}

// =====================================================================
// mid1: edge GEMM (0..95) + Q projection (96..351, 64-col tiles)
// =====================================================================
#define EG_B (64 * EGP)

__global__ void __launch_bounds__(256)
mid1_kernel(const float* __restrict__ bg, const float* __restrict__ bs,
            const float* __restrict__ bh, const float* __restrict__ bq,
            const float* __restrict__ X)
{
    extern __shared__ __align__(16) char sm[];
    const unsigned smb = smem_u32(sm);
    const int bid = blockIdx.x, t = threadIdx.x, w = t >> 5, lane = t & 31;

    if (bid >= 96) {
        const int idx = bid - 96;
        gemm64_body(0, bq, nullptr, X, (idx & 63) * 32, idx >> 6, sm, smb);
        return;
    }
    PDL_WAIT();
    const int m0 = (bid % 16) * 64, ny = bid / 16;
    #pragma unroll
    for (int i = 0; i < 4; i++) {
        int idx = t + i * 256;
        int r = idx >> 4, c = idx & 15;
        *reinterpret_cast<uint4*>(sm + (size_t)r * EGP + c * 16) =
            reinterpret_cast<const uint4*>(g_EFh + (size_t)(m0 + r) * 128)[c];
    }
    #pragma unroll
    for (int i = 0; i < 8; i++) {
        int idx = t + i * 256;
        int r = idx >> 4, c = idx & 15;
        *reinterpret_cast<uint4*>(sm + EG_B + (size_t)r * EGP + c * 16) =
            reinterpret_cast<const uint4*>(g_Wet + (size_t)(ny * 128 + r) * 128)[c];
    }
    __syncthreads();

    const int wm = (w & 1) * 32, wn = (w >> 1) * 32;
    float acc[2][4][4];
    #pragma unroll
    for (int mt = 0; mt < 2; mt++)
        #pragma unroll
        for (int n = 0; n < 4; n++)
            #pragma unroll
            for (int e = 0; e < 4; e++) acc[mt][n][e] = 0.0f;
    const unsigned aA = smb + (unsigned)(wm + (lane & 15)) * EGP + (lane >> 4) * 16;
    const unsigned bA = smb + EG_B + (unsigned)(wn + (lane & 7) + ((lane >> 4) << 3)) * EGP
                        + ((lane >> 3) & 1) * 16;
    #pragma unroll
    for (int ks = 0; ks < 8; ks++) {
        const unsigned ko = ks * 32u;
        unsigned a0[4], a1[4], bb[4];
        ldsm4(a0, aA + ko);
        ldsm4(a1, aA + 16u * EGP + ko);
        #pragma unroll
        for (int g = 0; g < 2; g++) {
            ldsm4(bb, bA + g * (16u * EGP) + ko);
            mma16816(acc[0][2 * g],     a0, bb[0], bb[1]);
            mma16816(acc[0][2 * g + 1], a0, bb[2], bb[3]);
            mma16816(acc[1][2 * g],     a1, bb[0], bb[1]);
            mma16816(acc[1][2 * g + 1], a1, bb[2], bb[3]);
        }
    }
    const float* bp = (ny < 2) ? bg : (ny < 4) ? bs : bh;
    const int boff = (ny & 1) * 128;
    #pragma unroll
    for (int mt = 0; mt < 2; mt++)
        #pragma unroll
        for (int nt = 0; nt < 4; nt++) {
            const int col = wn + nt * 8 + (lane & 3) * 2;
            const int C = ny * 128 + col;
            const int r0 = m0 + wm + mt * 16 + (lane >> 2);
            const float b0 = bp[boff + col], b1 = bp[boff + col + 1];
            *reinterpret_cast<float2*>(&g_pre[(size_t)r0 * 768 + C]) =
                make_float2(acc[mt][nt][0] + b0, acc[mt][nt][1] + b1);
            *reinterpret_cast<float2*>(&g_pre[(size_t)(r0 + 8) * 768 + C]) =
                make_float2(acc[mt][nt][2] + b0, acc[mt][nt][3] + b1);
        }
    PDL_LAUNCH();
}

// =====================================================================
// mid2: r kernel (0..255) + edge combine (256..1279)
// =====================================================================
__global__ void __launch_bounds__(256)
mid2_kernel(const float* __restrict__ EF,
            const float* __restrict__ Wbias, const float* __restrict__ bbias,
            const float* __restrict__ Whead, const float* __restrict__ bhead,
            const float* __restrict__ bk)
{
    __shared__ __align__(16) __half As[64 * 40];
    __shared__ __align__(16) __half Bs[256 * 40];
    __shared__ float ef[EE];
    const int bid = blockIdx.x, t = threadIdx.x, w = t >> 5, lane = t & 31;

    if (bid >= 256) {
        const int b = bid - 256;
        if (t < EE) ef[t] = EF[(size_t)b * EE + t];
        PDL_WAIT();
        __syncthreads();
        const float G = g_pre[(size_t)b * 768 + t];
        const float S = g_pre[(size_t)b * 768 + 256 + t];
        const float H = g_pre[(size_t)b * 768 + 512 + t];
        const float gate = 1.0f / (1.0f + __expf(-G));
        g_a [b * DD + t] = gate * (1.0f + tanhf(S));
        g_s2[b * DD + t] = gate * H;

        float ab = 0.0f, ah = 0.0f;
        #pragma unroll
        for (int j = 0; j < 4; j++) {
            const int e = lane + 32 * j;
            const float f = ef[e];
            ab += f * Wbias[e * NHH + w];
            ah += f * Whead[e * NHH + w];
        }
        #pragma unroll
        for (int o = 16; o > 0; o >>= 1) {
            ab += __shfl_xor_sync(0xffffffffu, ab, o);
            ah += __shfl_xor_sync(0xffffffffu, ah, o);
        }
        if (lane == 0) {
            g_eb[b * NHH + w] = bbias[w] + ab;
            g_hs[b * NHH + w] = (1.0f + tanhf(bhead[w] + ah)) * INV_SQRT_HD;
        }
        PDL_LAUNCH();
        return;
    }
    const int m0 = (bid & 31) * 64, h = bid >> 5;
    #pragma unroll
    for (int i = 0; i < 4; i++) {
        int idx = t + i * 256;
        int r = idx >> 2, c4 = idx & 3;
        reinterpret_cast<uint4*>(Bs + r * 40)[c4] =
            reinterpret_cast<const uint4*>(g_Wkn + (size_t)r * 256 + h * 32)[c4];
    }
    PDL_WAIT();
    {
        int r = t >> 2, c4 = t & 3;
        reinterpret_cast<uint4*>(As + r * 40)[c4] =
            reinterpret_cast<const uint4*>(g_Qh + (size_t)(m0 + r) * 256 + h * 32)[c4];
    }
    __syncthreads();

    if (t < 64) {
        float s = 0.0f;
        #pragma unroll
        for (int d = 0; d < 32; d++)
            s += __half2float(As[t * 40 + d]) * bk[h * 32 + d];
        g_bkd[(size_t)((m0 + t) >> 1) * 16 + h * 2 + ((m0 + t) & 1)] = s;
    }

    const int wm = (w & 3) * 16, wn = (w >> 2) * 128;
    float acc[16][4];
    #pragma unroll
    for (int n = 0; n < 16; n++)
        #pragma unroll
        for (int e = 0; e < 4; e++) acc[n][e] = 0.0f;
    const unsigned aA = smem_u32(As) + (unsigned)(wm + (lane & 15)) * 80 + (lane >> 4) * 16;
    const unsigned bA = smem_u32(Bs) + (unsigned)(wn + (lane & 7) + ((lane >> 4) << 3)) * 80
                        + ((lane >> 3) & 1) * 16;
    #pragma unroll
    for (int ks = 0; ks < 2; ks++) {
        const unsigned ko = ks * 32u;
        unsigned a[4];
        ldsm4(a, aA + ko);
        #pragma unroll
        for (int g = 0; g < 8; g++) {
            unsigned bb[4];
            ldsm4(bb, bA + g * (16u * 80) + ko);
            mma16816(acc[2 * g],     a, bb[0], bb[1]);
            mma16816(acc[2 * g + 1], a, bb[2], bb[3]);
        }
    }
    #pragma unroll
    for (int nt = 0; nt < 16; nt++) {
        const int c = wn + nt * 8 + (lane & 3) * 2;
        #pragma unroll
        for (int half_ = 0; half_ < 2; half_++) {
            const int rr = m0 + wm + (lane >> 2) + half_ * 8;
            const int bidx = rr >> 1, p = h * 2 + (rr & 1);
            *reinterpret_cast<__half2*>(&g_R[((size_t)bidx * 16 + p) * 256 + c]) =
                __floats2half2_rn(acc[nt][2 * half_], acc[nt][2 * half_ + 1]);
        }
    }
    PDL_LAUNCH();
}

// =====================================================================
// FUSED (R11 verbatim): scores + softmax + y.  X staged BEFORE PDL wait.
// =====================================================================
#define FX_XH   0
#define FX_R    67584
#define FX_P    (67584 + 8448)
#define FX_S    (76032 + 8704)
#define FX_MISC (84736 + 8192)
#define FX_SMEM (92928 + 128)

__global__ void __launch_bounds__(256, 2)
fused_kernel(const float* __restrict__ X)
{
    extern __shared__ __align__(16) char sm[];
    const unsigned smb = smem_u32(sm);
    float* S   = reinterpret_cast<float*>(sm + FX_S);
    float* msc = reinterpret_cast<float*>(sm + FX_MISC);
    const int t = threadIdx.x, w = t >> 5, lane = t & 31;
    const int b = blockIdx.x;

    const float4* X4 = reinterpret_cast<const float4*>(X) + (size_t)b * SS * 64;
    #pragma unroll
    for (int i = 0; i < 32; i++) {
        int idx = t + i * 256;
        int r = idx >> 6, kq = idx & 63;
        float4 v = X4[idx];
        __half2 h0 = __floats2half2_rn(v.x, v.y);
        __half2 h1 = __floats2half2_rn(v.z, v.w);
        uint2 pk;
        pk.x = *reinterpret_cast<unsigned*>(&h0);
        pk.y = *reinterpret_cast<unsigned*>(&h1);
        *reinterpret_cast<uint2*>(sm + FX_XH + (size_t)r * RSB + kq * 8) = pk;
    }
    PDL_WAIT();
    if (t < 8)       msc[t] = g_eb[b * NHH + t];
    else if (t < 16) msc[t] = g_hs[b * NHH + (t - 8)];
    else if (t < 32) msc[t] = g_bkd[(size_t)b * 16 + (t - 16)];
    #pragma unroll
    for (int i = 0; i < 2; i++) {
        int idx = t + i * 256;
        int r = idx >> 5, c = idx & 31;
        *reinterpret_cast<uint4*>(sm + FX_R + (size_t)r * RSB + c * 16) =
            reinterpret_cast<const uint4*>(g_R + ((size_t)b * 16 + r) * 256)[c];
    }
    __syncthreads();

    {
        float sa[2][4];
        #pragma unroll
        for (int n = 0; n < 2; n++)
            #pragma unroll
            for (int e = 0; e < 4; e++) sa[n][e] = 0.0f;
        const unsigned aA = smb + FX_R + (unsigned)(lane & 15) * RSB + (lane >> 4) * 16;
        const unsigned bA = smb + FX_XH + (unsigned)(w * 16 + (lane & 7) + ((lane >> 4) << 3)) * RSB
                            + ((lane >> 3) & 1) * 16;
        #pragma unroll
        for (int ks = 0; ks < 16; ks++) {
            const unsigned ko = ks * 32u;
            unsigned a[4], bb[4];
            ldsm4(a, aA + ko);
            ldsm4(bb, bA + ko);
            mma16816(sa[0], a, bb[0], bb[1]);
            mma16816(sa[1], a, bb[2], bb[3]);
        }
        #pragma unroll
        for (int nt = 0; nt < 2; nt++) {
            const int c0 = w * 16 + nt * 8 + (lane & 3) * 2;
            const int p0 = lane >> 2;
            S[p0 * 128 + c0]           = sa[nt][0];
            S[p0 * 128 + c0 + 1]       = sa[nt][1];
            S[(p0 + 8) * 128 + c0]     = sa[nt][2];
            S[(p0 + 8) * 128 + c0 + 1] = sa[nt][3];
        }
    }
    __syncthreads();

    #pragma unroll
    for (int qi = 0; qi < 2; qi++) {
        const int p = w * 2 + qi;
        const int kb = qi ? 63 : 127;
        float sv[4];
        #pragma unroll
        for (int j = 0; j < 4; j++) {
            const int k = lane + 32 * j;
            float s = (S[p * 128 + k] + msc[16 + p]) * msc[8 + w];
            if (k == kb) s += msc[w];
            sv[j] = s;
        }
        float m = fmaxf(fmaxf(sv[0], sv[1]), fmaxf(sv[2], sv[3]));
        #pragma unroll
        for (int o = 16; o > 0; o >>= 1) m = fmaxf(m, __shfl_xor_sync(0xffffffffu, m, o));
        float e[4], sum = 0.0f;
        #pragma unroll
        for (int j = 0; j < 4; j++) { e[j] = __expf(sv[j] - m); sum += e[j]; }
        #pragma unroll
        for (int o = 16; o > 0; o >>= 1) sum += __shfl_xor_sync(0xffffffffu, sum, o);
        const float inv = 1.0f / sum;
        #pragma unroll
        for (int j = 0; j < 4; j++) {
            const int k = lane + 32 * j;
            const float pv = e[j] * inv;
            const __half hi = __float2half_rn(pv);
            const __half lo = __float2half_rn(pv - __half2float(hi));
            *reinterpret_cast<__half*>(sm + FX_P + (size_t)p * 272 + k * 2) = hi;
            *reinterpret_cast<__half*>(sm + FX_P + (size_t)(p + 16) * 272 + k * 2) = lo;
        }
    }
    __syncthreads();

    {
        float ya[2][4][4];
        #pragma unroll
        for (int mt = 0; mt < 2; mt++)
            #pragma unroll
            for (int n = 0; n < 4; n++)
                #pragma unroll
                for (int e = 0; e < 4; e++) ya[mt][n][e] = 0.0f;
        const unsigned pA = smb + FX_P + (unsigned)(lane & 15) * 272 + (lane >> 4) * 16;
        const unsigned bT = smb + FX_XH
            + (unsigned)((lane & 7) + ((lane >> 3) & 1) * 8) * RSB
            + (lane >> 4) * 16 + (unsigned)(w * 32) * 2;
        #pragma unroll
        for (int ks = 0; ks < 8; ks++) {
            unsigned a0[4], a1[4], b0[4], b1[4];
            ldsm4(a0, pA + ks * 32u);
            ldsm4(a1, pA + 16u * 272 + ks * 32u);
            ldsm4t(b0, bT + ks * (16u * RSB));
            ldsm4t(b1, bT + 32u + ks * (16u * RSB));
            mma16816(ya[0][0], a0, b0[0], b0[1]);
            mma16816(ya[0][1], a0, b0[2], b0[3]);
            mma16816(ya[0][2], a0, b1[0], b1[1]);
            mma16816(ya[0][3], a0, b1[2], b1[3]);
            mma16816(ya[1][0], a1, b0[0], b0[1]);
            mma16816(ya[1][1], a1, b0[2], b0[3]);
            mma16816(ya[1][2], a1, b1[0], b1[1]);
            mma16816(ya[1][3], a1, b1[2], b1[3]);
        }
        #pragma unroll
        for (int nt = 0; nt < 4; nt++) {
            const int c0 = w * 32 + nt * 8 + (lane & 3) * 2;
            const int p0 = lane >> 2;
            *reinterpret_cast<__half2*>(&g_Y[((size_t)b * 16 + p0) * 256 + c0]) =
                __floats2half2_rn(ya[0][nt][0] + ya[1][nt][0], ya[0][nt][1] + ya[1][nt][1]);
            *reinterpret_cast<__half2*>(&g_Y[((size_t)b * 16 + p0 + 8) * 256 + c0]) =
                __floats2half2_rn(ya[0][nt][2] + ya[1][nt][2], ya[0][nt][3] + ya[1][nt][3]);
        }
    }
    PDL_LAUNCH();
}

// =====================================================================
// AOh: per-head GEMM with gating epilogue.  B first, wait, then A.
// =====================================================================
#define AO_B    33792u
#define AO_SMEM (33792 + 32 * RSB)

__global__ void __launch_bounds__(256)
aoh_kernel(const float* __restrict__ bv)
{
    extern __shared__ __align__(16) char sm[];
    const unsigned smb = smem_u32(sm);
    const int t = threadIdx.x, w = t >> 5, lane = t & 31;
    const int b0 = (blockIdx.x & 31) * 32, h = blockIdx.x >> 5;

    #pragma unroll
    for (int i = 0; i < 4; i++) {
        int idx = t + i * 256;
        int r = idx >> 5, c = idx & 31;
        *reinterpret_cast<uint4*>(sm + AO_B + (size_t)r * RSB + c * 16) =
            reinterpret_cast<const uint4*>(g_Wt + (size_t)(256 + h * 32 + r) * 256)[c];
    }
    PDL_WAIT();
    #pragma unroll
    for (int i = 0; i < 8; i++) {
        int idx = t + i * 256;
        int rr = idx >> 5, c = idx & 31;
        const size_t src = ((size_t)(b0 + (rr >> 1)) * 16 + h * 2 + (rr & 1)) * 256;
        *reinterpret_cast<uint4*>(sm + (size_t)rr * RSB + c * 16) =
            reinterpret_cast<const uint4*>(g_Y + src)[c];
    }
    __syncthreads();

    const int wm = (w & 3) * 16, wn = (w >> 2) * 16;
    float acc[2][4];
    #pragma unroll
    for (int n = 0; n < 2; n++)
        #pragma unroll
        for (int e = 0; e < 4; e++) acc[n][e] = 0.0f;
    const unsigned aA = smb + (unsigned)(wm + (lane & 15)) * RSB + (lane >> 4) * 16;
    const unsigned bA = smb + AO_B + (unsigned)(wn + (lane & 7) + ((lane >> 4) << 3)) * RSB
                        + ((lane >> 3) & 1) * 16;
    #pragma unroll
    for (int ks = 0; ks < 16; ks++) {
        const unsigned ko = ks * 32u;
        unsigned a[4], bb[4];
        ldsm4(a, aA + ko);
        ldsm4(bb, bA + ko);
        mma16816(acc[0], a, bb[0], bb[1]);
        mma16816(acc[1], a, bb[2], bb[3]);
    }
    #pragma unroll
    for (int nt = 0; nt < 2; nt++) {
        const int col = wn + nt * 8 + (lane & 3) * 2;
        const int C = h * 32 + col;
        const float b0f = bv[C], b1f = bv[C + 1];
        #pragma unroll
        for (int half_ = 0; half_ < 2; half_++) {
            const int rr = wm + (lane >> 2) + half_ * 8;
            const int bb_ = b0 + (rr >> 1), qi = rr & 1;
            const float a0 = g_a[bb_ * DD + C],  a1 = g_a[bb_ * DD + C + 1];
            const float s0 = g_s2[bb_ * DD + C], s1 = g_s2[bb_ * DD + C + 1];
            *reinterpret_cast<__half2*>(&g_AO[(size_t)(bb_ * 2 + qi) * 256 + C]) =
                __floats2half2_rn((acc[nt][2 * half_]     + b0f) * a0 + s0,
                                  (acc[nt][2 * half_ + 1] + b1f) * a1 + s1);
        }
    }
    PDL_LAUNCH();
}

// =====================================================================
// final: O projection (64-col tiles, 256 CTAs)
// =====================================================================
__global__ void __launch_bounds__(256)
final_kernel(const float* __restrict__ bo, float* __restrict__ out,
             const float* __restrict__ X)
{
    extern __shared__ __align__(16) char sm[];
    gemm64_body(1, bo, out, X, (blockIdx.x & 63) * 32, blockIdx.x >> 6,
                sm, smem_u32(sm));
}

// =====================================================================
extern "C" void kernel_launch(void* const* d_in, const int* in_sizes, int n_in,
                              void* d_out, int out_size)
{
    (void)in_sizes; (void)n_in; (void)out_size;
    const float* X      = (const float*)d_in[0];
    const float* EF     = (const float*)d_in[1];
    const float* Wq     = (const float*)d_in[2];
    const float* bq     = (const float*)d_in[3];
    const float* Wk     = (const float*)d_in[4];
    const float* bk     = (const float*)d_in[5];
    const float* Wv     = (const float*)d_in[6];
    const float* bv     = (const float*)d_in[7];
    const float* Wo     = (const float*)d_in[8];
    const float* bo     = (const float*)d_in[9];
    const float* Wbias  = (const float*)d_in[10];
    const float* bbias  = (const float*)d_in[11];
    const float* Wgate  = (const float*)d_in[12];
    const float* bgate  = (const float*)d_in[13];
    const float* Wscale = (const float*)d_in[14];
    const float* bscale = (const float*)d_in[15];
    const float* Wshift = (const float*)d_in[16];
    const float* bshift = (const float*)d_in[17];
    const float* Whead  = (const float*)d_in[18];
    const float* bhead  = (const float*)d_in[19];
    float* out = (float*)d_out;

    cudaFuncSetAttribute(mid1_kernel,  cudaFuncAttributeMaxDynamicSharedMemorySize, MID1_SMEM);
    cudaFuncSetAttribute(fused_kernel, cudaFuncAttributeMaxDynamicSharedMemorySize, FX_SMEM);
    cudaFuncSetAttribute(aoh_kernel,   cudaFuncAttributeMaxDynamicSharedMemorySize, AO_SMEM);
    cudaFuncSetAttribute(final_kernel, cudaFuncAttributeMaxDynamicSharedMemorySize, G64_SMEM);

    prep_kernel<<<608, 256>>>(Wk, Wv, Wq, Wo, Wgate, Wscale, Wshift, EF);

    cudaLaunchAttribute at[1];
    at[0].id = cudaLaunchAttributeProgrammaticStreamSerialization;
    at[0].val.programmaticStreamSerializationAllowed = 1;
    cudaLaunchConfig_t cfg = {};
    cfg.blockDim = dim3(256, 1, 1);
    cfg.attrs = at;
    cfg.numAttrs = 1;
    cfg.stream = 0;

    cfg.gridDim = dim3(352, 1, 1); cfg.dynamicSmemBytes = MID1_SMEM;
    cudaLaunchKernelEx(&cfg, mid1_kernel, bgate, bscale, bshift, bq, X);

    cfg.gridDim = dim3(1280, 1, 1); cfg.dynamicSmemBytes = 0;
    cudaLaunchKernelEx(&cfg, mid2_kernel, EF, Wbias, bbias, Whead, bhead, bk);

    cfg.gridDim = dim3(1024, 1, 1); cfg.dynamicSmemBytes = FX_SMEM;
    cudaLaunchKernelEx(&cfg, fused_kernel, X);

    cfg.gridDim = dim3(256, 1, 1); cfg.dynamicSmemBytes = AO_SMEM;
    cudaLaunchKernelEx(&cfg, aoh_kernel, bv);

    cfg.gridDim = dim3(256, 1, 1); cfg.dynamicSmemBytes = G64_SMEM;
    cudaLaunchKernelEx(&cfg, final_kernel, bo, out, X);
}